// round 7
// baseline (speedup 1.0000x reference)
#include <cuda_runtime.h>
#include <cuda_bf16.h>
#include <math.h>
#include <stdint.h>

#define NN 50000
#define NE 800000
#define C 128

// Scratch (device globals; no allocation allowed)
// NOTE: g_M1/2/3 hold the folded matrices TRANSPOSED: g_M[j*C + i] = M[i][j]
__device__ float g_M1[C * C];
__device__ float g_M2[C * C];
__device__ float g_M3[C * C];
__device__ float g_cb[C];
__device__ float g_A[NN * C];
__device__ float g_B[NN * C];

__device__ __forceinline__ uint32_t smem_u32(const void* p) {
    uint32_t a;
    asm("{ .reg .u64 t; cvta.to.shared.u64 t, %1; cvt.u32.u64 %0, t; }"
        : "=r"(a) : "l"(p));
    return a;
}
__device__ __forceinline__ void ldsm_x4(uint32_t* r, uint32_t addr) {
    asm volatile("ldmatrix.sync.aligned.m8n8.x4.shared.b16 {%0,%1,%2,%3}, [%4];"
                 : "=r"(r[0]), "=r"(r[1]), "=r"(r[2]), "=r"(r[3]) : "r"(addr));
}
__device__ __forceinline__ void mma_bf16(float* c, const uint32_t* a,
                                         uint32_t b0, uint32_t b1) {
    asm volatile(
        "mma.sync.aligned.m16n8k16.row.col.f32.bf16.bf16.f32 "
        "{%0,%1,%2,%3}, {%4,%5,%6,%7}, {%8,%9}, {%0,%1,%2,%3};"
        : "+f"(c[0]), "+f"(c[1]), "+f"(c[2]), "+f"(c[3])
        : "r"(a[0]), "r"(a[1]), "r"(a[2]), "r"(a[3]), "r"(b0), "r"(b1));
}
__device__ __forceinline__ void bar_pair(int id) {
    asm volatile("bar.sync %0, %1;" :: "r"(id), "r"(64) : "memory");
}

#define PITCH 272

// ---------------------------------------------------------------------------
// K1: fold the three input linears through enc_W. Stores TRANSPOSED:
// g_M[j*C+i] = sum_h W[i][h] * E[h][j]  (so node kernel reads coalesced).
// ---------------------------------------------------------------------------
__global__ void fold_kernel(const float* __restrict__ node_W,
                            const float* __restrict__ nbr_W,
                            const float* __restrict__ gud_W,
                            const float* __restrict__ enc_W) {
    int m = blockIdx.y;
    const float* W = (m == 0) ? node_W : ((m == 1) ? nbr_W : gud_W);
    const float* E = enc_W + m * C * C;
    float* M = (m == 0) ? g_M1 : ((m == 1) ? g_M2 : g_M3);

    int j = threadIdx.x & 127;
    int iq = threadIdx.x >> 7;
    int i0 = blockIdx.x * 32;
    for (int i = i0 + iq; i < i0 + 32; i += 2) {
        float s = 0.f;
#pragma unroll 4
        for (int h = 0; h < C; h++) s += W[i * C + h] * E[h * C + j];
        M[j * C + i] = s;   // transposed store
    }
}

__global__ void cb_kernel(const float* __restrict__ node_b,
                          const float* __restrict__ nbr_b,
                          const float* __restrict__ gud_b,
                          const float* __restrict__ enc_W,
                          const float* __restrict__ enc_b) {
    int j = threadIdx.x;
    float s = enc_b[j];
    for (int h = 0; h < C; h++) s += node_b[h] * enc_W[h * C + j];
    for (int h = 0; h < C; h++) s += nbr_b[h] * enc_W[(C + h) * C + j];
    for (int h = 0; h < C; h++) s += gud_b[h] * enc_W[(2 * C + h) * C + j];
    g_cb[j] = s;
}

// ---------------------------------------------------------------------------
// K2: persistent split-bf16 node precompute. 148 blocks x 256 threads.
// Phases: 0: g_A = x@M1 ; 1: g_B = x@M2 ; 2: g_B += g@M3 (same-thread RMW).
// Weight staging reads g_M (transposed content) COALESCED.
// ---------------------------------------------------------------------------
#define NW_H   0
#define NX0    69632
#define NSMEM  208896
#define NODE_GRID 148

__global__ __launch_bounds__(256, 1)
void node_mma_persist(const float* __restrict__ x, const float* __restrict__ g) {
    extern __shared__ float smf[];
    char* smc = (char*)smf;
    uint32_t su = smem_u32(smf);
    int tid = threadIdx.x;
    int tx = tid & 31, wid = tid >> 5;
    int mg = wid & 3, nh = wid >> 2;

    uint32_t a_row = (tx & 7) + 8 * ((tx >> 3) & 1);
    uint32_t a_k16 = (tx >> 4) * 16;
    uint32_t b_row = (tx & 7) + 8 * (tx >> 4);
    uint32_t b_k16 = ((tx >> 3) & 1) * 16;

    const int NT = (NN + 127) / 128;  // 391

    for (int ph = 0; ph < 3; ph++) {
        const float* Wm = (ph == 0) ? g_M1 : ((ph == 1) ? g_M2 : g_M3);
        const float* src = (ph == 2) ? g : x;
        float* dst = (ph == 0) ? g_A : g_B;

        __syncthreads();  // prior phase's MMA reads of W done
        // stage weights [n][k] split bf16 — coalesced read of transposed g_M
        for (int idx = tid; idx < C * C; idx += 256) {
            int n = idx >> 7, k = idx & 127;
            float w = Wm[idx];  // = Wm[n*C+k]
            __nv_bfloat16 h = __float2bfloat16(w);
            __nv_bfloat16 l = __float2bfloat16(w - __bfloat162float(h));
            *(__nv_bfloat16*)(smc + NW_H + n * PITCH + k * 2) = h;
            *(__nv_bfloat16*)(smc + NW_H + 34816 + n * PITCH + k * 2) = l;
        }

        int it = 0;
        for (int t = blockIdx.x; t < NT; t += NODE_GRID, it++) {
            int node0 = t * 128;
            char* xb = smc + NX0 + (it & 1) * 69632;

            for (int idx = tid; idx < 128 * 32; idx += 256) {
                int row = idx >> 5, c4 = idx & 31;
                int n = node0 + row;
                float4 v = make_float4(0.f, 0.f, 0.f, 0.f);
                if (n < NN) v = ((const float4*)(src + (size_t)n * C))[c4];
                __nv_bfloat162 h01 = __floats2bfloat162_rn(v.x, v.y);
                __nv_bfloat162 h23 = __floats2bfloat162_rn(v.z, v.w);
                __nv_bfloat162 l01 = __floats2bfloat162_rn(
                    v.x - __bfloat162float(h01.x), v.y - __bfloat162float(h01.y));
                __nv_bfloat162 l23 = __floats2bfloat162_rn(
                    v.z - __bfloat162float(h23.x), v.w - __bfloat162float(h23.y));
                uint2 hv, lv;
                hv.x = *(uint32_t*)&h01; hv.y = *(uint32_t*)&h23;
                lv.x = *(uint32_t*)&l01; lv.y = *(uint32_t*)&l23;
                *(uint2*)(xb + row * PITCH + c4 * 8) = hv;
                *(uint2*)(xb + 34816 + row * PITCH + c4 * 8) = lv;
            }
            __syncthreads();

            float acc[16][4];
#pragma unroll
            for (int a = 0; a < 16; a++)
#pragma unroll
                for (int b = 0; b < 4; b++) acc[a][b] = 0.f;

            uint32_t aB = su + (uint32_t)(xb - smc) + (mg * 32) * PITCH;
            uint32_t aBL = aB + 34816;
            uint32_t wB = su + NW_H;
            uint32_t wBL = wB + 34816;

            for (int ks = 0; ks < 8; ks++) {
                uint32_t colA = ks * 32 + a_k16;
                uint32_t ah0[4], al0[4], ah1[4], al1[4];
                ldsm_x4(ah0, aB + a_row * PITCH + colA);
                ldsm_x4(al0, aBL + a_row * PITCH + colA);
                ldsm_x4(ah1, aB + (16 + a_row) * PITCH + colA);
                ldsm_x4(al1, aBL + (16 + a_row) * PITCH + colA);
#pragma unroll
                for (int np = 0; np < 4; np++) {
                    uint32_t bro = (nh * 64 + np * 16 + b_row) * PITCH + ks * 32 + b_k16;
                    uint32_t bh[4], bl[4];
                    ldsm_x4(bh, wB + bro);
                    ldsm_x4(bl, wBL + bro);
                    int i0 = np * 4;
                    mma_bf16(acc[i0 + 0], ah0, bh[0], bh[1]);
                    mma_bf16(acc[i0 + 0], al0, bh[0], bh[1]);
                    mma_bf16(acc[i0 + 0], ah0, bl[0], bl[1]);
                    mma_bf16(acc[i0 + 1], ah0, bh[2], bh[3]);
                    mma_bf16(acc[i0 + 1], al0, bh[2], bh[3]);
                    mma_bf16(acc[i0 + 1], ah0, bl[2], bl[3]);
                    mma_bf16(acc[i0 + 2], ah1, bh[0], bh[1]);
                    mma_bf16(acc[i0 + 2], al1, bh[0], bh[1]);
                    mma_bf16(acc[i0 + 2], ah1, bl[0], bl[1]);
                    mma_bf16(acc[i0 + 3], ah1, bh[2], bh[3]);
                    mma_bf16(acc[i0 + 3], al1, bh[2], bh[3]);
                    mma_bf16(acc[i0 + 3], ah1, bl[2], bl[3]);
                }
            }

#pragma unroll
            for (int np = 0; np < 4; np++) {
#pragma unroll
                for (int fr = 0; fr < 4; fr++) {
                    int mm = fr >> 1, pr = fr & 1;
                    int col = nh * 64 + np * 16 + pr * 8 + 2 * (tx & 3);
#pragma unroll
                    for (int j2 = 0; j2 < 2; j2++) {
                        int row = node0 + mg * 32 + mm * 16 + (tx >> 2) + j2 * 8;
                        if (row < NN) {
                            float2 v = make_float2(acc[np * 4 + fr][j2 * 2],
                                                   acc[np * 4 + fr][j2 * 2 + 1]);
                            float* p = &dst[(size_t)row * C + col];
                            if (ph == 2) {
                                float2 o = *(float2*)p;
                                v.x += o.x; v.y += o.y;
                            }
                            *(float2*)p = v;
                        }
                    }
                }
            }
        }
    }
}

// ---------------------------------------------------------------------------
// K3: split-bf16 edge kernel, warp-pair structure with named barriers.
// 320 threads = 10 warps = 5 pairs. Pair owns 32 edges; warp computes a
// 96-col half over all 32 rows. 160 edges/tile x 5000 tiles = NE exactly.
// SMEM bytes:
//   [0..1536)     params (vb1,vw2,pb1,pw2)
//   [1536..2176)  lpbuf: 5 pairs x 32 floats
//   [2560..)      A: 5 pairs x (hi 32x272 + lo 32x272) = 17408/pair
//   [89600..)     B hi 192x272 ; [141824..) B lo ; end 194048
// ---------------------------------------------------------------------------
#define LP_OFF   384
#define A_OFF    2560
#define A_PAIR   17408
#define B_H_OFF  (A_OFF + 5 * A_PAIR)       // 89600
#define B_L_OFF  (B_H_OFF + 192 * PITCH)    // 141824
#define SMEM_E   (B_L_OFF + 192 * PITCH)    // 194048
#define NGRID    148

__global__ __launch_bounds__(320, 1)
void edge_kernel_mma(const int* __restrict__ ei,
                     const float* __restrict__ vp_W1, const float* __restrict__ vp_b1,
                     const float* __restrict__ vp_W2, const float* __restrict__ vp_b2,
                     const float* __restrict__ pol_W1, const float* __restrict__ pol_b1,
                     const float* __restrict__ pol_W2, const float* __restrict__ pol_b2,
                     float* __restrict__ out) {
    extern __shared__ float smf[];
    char* smc = (char*)smf;
    uint32_t su = smem_u32(smf);
    int tid = threadIdx.x;
    int tx = tid & 31, wid = tid >> 5;
    int pr_id = wid >> 1, w01 = wid & 1;

    // --- stage split weights B[n][k] ---
    for (int idx = tid; idx < 192 * C; idx += 320) {
        int n = idx >> 7, k = idx & 127;
        float w = (n < 64) ? vp_W1[k * 64 + n] : pol_W1[k * C + (n - 64)];
        __nv_bfloat16 wh = __float2bfloat16(w);
        __nv_bfloat16 wl = __float2bfloat16(w - __bfloat162float(wh));
        *(__nv_bfloat16*)(smc + B_H_OFF + n * PITCH + k * 2) = wh;
        *(__nv_bfloat16*)(smc + B_L_OFF + n * PITCH + k * 2) = wl;
    }
    if (tid < 64) { smf[tid] = vp_b1[tid]; smf[64 + tid] = vp_W2[tid]; }
    if (tid < 128) { smf[128 + tid] = pol_b1[tid]; smf[256 + tid] = pol_W2[tid]; }
    __syncthreads();

    float vb2v = vp_b2[0], pb2v = pol_b2[0];
    float4 cb4 = ((const float4*)g_cb)[tx];
    if (blockIdx.x == 0 && tid == 0) out[3L * NE] = 0.f;  // value_loss

    uint32_t apair = su + A_OFF + pr_id * A_PAIR;
    uint32_t a_row = (tx & 7) + 8 * ((tx >> 3) & 1);
    uint32_t a_k16 = (tx >> 4) * 16;
    uint32_t b_row = (tx & 7) + 8 * (tx >> 4);
    uint32_t b_k16 = ((tx >> 3) & 1) * 16;
    int barid = pr_id + 1;

    const int ntiles = NE / 160;  // 5000 exact
    for (int t = blockIdx.x; t < ntiles; t += NGRID) {
        long tbase = (long)t * 160 + pr_id * 32;

        // ---- gather: warp fills its 16 rows of the pair's 32-row A ----
        {
            long gb = tbase + w01 * 16;
            uint32_t abase = (uint32_t)(apair - su);
#pragma unroll 4
            for (int m = 0; m < 16; m++) {
                int rr = ei[gb + m];
                int cc = ei[NE + gb + m];
                float4 a = ((const float4*)(g_A + (size_t)rr * C))[tx];
                float4 b = ((const float4*)(g_B + (size_t)cc * C))[tx];
                float z0 = fmaxf(a.x + b.x + cb4.x, 0.f);
                float z1 = fmaxf(a.y + b.y + cb4.y, 0.f);
                float z2 = fmaxf(a.z + b.z + cb4.z, 0.f);
                float z3 = fmaxf(a.w + b.w + cb4.w, 0.f);
                __nv_bfloat162 h01 = __floats2bfloat162_rn(z0, z1);
                __nv_bfloat162 h23 = __floats2bfloat162_rn(z2, z3);
                __nv_bfloat162 l01 = __floats2bfloat162_rn(
                    z0 - __bfloat162float(h01.x), z1 - __bfloat162float(h01.y));
                __nv_bfloat162 l23 = __floats2bfloat162_rn(
                    z2 - __bfloat162float(h23.x), z3 - __bfloat162float(h23.y));
                int row = w01 * 16 + m;
                uint2 hv, lv;
                hv.x = *(uint32_t*)&h01; hv.y = *(uint32_t*)&h23;
                lv.x = *(uint32_t*)&l01; lv.y = *(uint32_t*)&l23;
                *(uint2*)(smc + abase + row * PITCH + tx * 8) = hv;
                *(uint2*)(smc + abase + 8704 + row * PITCH + tx * 8) = lv;
            }
        }
        bar_pair(barid);  // pair's A complete

        // ---- MMA: all 32 rows x this warp's 96-col half ----
        float acc[2][6][2][4];
#pragma unroll
        for (int mg = 0; mg < 2; mg++)
#pragma unroll
            for (int np = 0; np < 6; np++)
#pragma unroll
                for (int pr = 0; pr < 2; pr++)
#pragma unroll
                    for (int q = 0; q < 4; q++) acc[mg][np][pr][q] = 0.f;

        for (int ks = 0; ks < 8; ks++) {
            uint32_t colA = ks * 32 + a_k16;
            uint32_t ah0[4], al0[4], ah1[4], al1[4];
            ldsm_x4(ah0, apair + a_row * PITCH + colA);
            ldsm_x4(al0, apair + 8704 + a_row * PITCH + colA);
            ldsm_x4(ah1, apair + (16 + a_row) * PITCH + colA);
            ldsm_x4(al1, apair + 8704 + (16 + a_row) * PITCH + colA);
            uint32_t bcol = ks * 32 + b_k16;
#pragma unroll
            for (int np = 0; np < 6; np++) {
                uint32_t bro = (w01 * 96 + np * 16 + b_row) * PITCH + bcol;
                uint32_t bh[4], bl[4];
                ldsm_x4(bh, su + B_H_OFF + bro);
                ldsm_x4(bl, su + B_L_OFF + bro);
                mma_bf16(acc[0][np][0], ah0, bh[0], bh[1]);
                mma_bf16(acc[0][np][0], al0, bh[0], bh[1]);
                mma_bf16(acc[0][np][0], ah0, bl[0], bl[1]);
                mma_bf16(acc[0][np][1], ah0, bh[2], bh[3]);
                mma_bf16(acc[0][np][1], al0, bh[2], bh[3]);
                mma_bf16(acc[0][np][1], ah0, bl[2], bl[3]);
                mma_bf16(acc[1][np][0], ah1, bh[0], bh[1]);
                mma_bf16(acc[1][np][0], al1, bh[0], bh[1]);
                mma_bf16(acc[1][np][0], ah1, bl[0], bl[1]);
                mma_bf16(acc[1][np][1], ah1, bh[2], bh[3]);
                mma_bf16(acc[1][np][1], al1, bh[2], bh[3]);
                mma_bf16(acc[1][np][1], ah1, bl[2], bl[3]);
            }
        }

        // ---- per-thread head partials ----
        float vpm[2][2] = {{0.f, 0.f}, {0.f, 0.f}};
        float lp[2][2] = {{0.f, 0.f}, {0.f, 0.f}};
#pragma unroll
        for (int mg = 0; mg < 2; mg++)
#pragma unroll
            for (int np = 0; np < 6; np++)
#pragma unroll
                for (int pr = 0; pr < 2; pr++) {
                    int gcol = w01 * 96 + np * 16 + pr * 8 + 2 * (tx & 3);
                    const float* a = acc[mg][np][pr];
                    if (gcol < 64) {
                        float b0 = smf[gcol], w0 = smf[64 + gcol];
                        float b1 = smf[gcol + 1], w1 = smf[64 + gcol + 1];
                        vpm[mg][0] += fmaxf(a[0] + b0, 0.f) * w0 + fmaxf(a[1] + b1, 0.f) * w1;
                        vpm[mg][1] += fmaxf(a[2] + b0, 0.f) * w0 + fmaxf(a[3] + b1, 0.f) * w1;
                    } else {
                        int ix = gcol - 64;
                        float b0 = smf[128 + ix], w0 = smf[256 + ix];
                        float b1 = smf[128 + ix + 1], w1 = smf[256 + ix + 1];
                        lp[mg][0] += fmaxf(a[0] + b0, 0.f) * w0 + fmaxf(a[1] + b1, 0.f) * w1;
                        lp[mg][1] += fmaxf(a[2] + b0, 0.f) * w0 + fmaxf(a[3] + b1, 0.f) * w1;
                    }
                }
#pragma unroll
        for (int off = 1; off <= 2; off <<= 1) {
#pragma unroll
            for (int mg = 0; mg < 2; mg++) {
                vpm[mg][0] += __shfl_xor_sync(0xffffffffu, vpm[mg][0], off);
                vpm[mg][1] += __shfl_xor_sync(0xffffffffu, vpm[mg][1], off);
                lp[mg][0] += __shfl_xor_sync(0xffffffffu, lp[mg][0], off);
                lp[mg][1] += __shfl_xor_sync(0xffffffffu, lp[mg][1], off);
            }
        }

        int r = tx >> 2;
        if (w01 == 1 && (tx & 3) == 0) {
#pragma unroll
            for (int mg = 0; mg < 2; mg++) {
                smf[LP_OFF + pr_id * 32 + mg * 16 + r] = lp[mg][0];
                smf[LP_OFF + pr_id * 32 + mg * 16 + 8 + r] = lp[mg][1];
            }
        }
        bar_pair(barid);  // lp ready; both warps' MMA done -> A reusable

        if (w01 == 0 && (tx & 3) == 0) {
#pragma unroll
            for (int mg = 0; mg < 2; mg++)
#pragma unroll
                for (int half = 0; half < 2; half++) {
                    int row = mg * 16 + half * 8 + r;
                    long e = tbase + row;
                    float v = vpm[mg][half] + vb2v;
                    float lpt = lp[mg][half] + smf[LP_OFF + pr_id * 32 + row] + pb2v;
                    float p = 1.f / (1.f + expf(-lpt));
                    out[e] = v;
                    out[NE + e] = p;
                    out[2L * NE + e] = (p > 0.5f) ? 1.f : 0.f;
                }
        }
    }
}

// ---------------------------------------------------------------------------
extern "C" void kernel_launch(void* const* d_in, const int* in_sizes, int n_in,
                              void* d_out, int out_size) {
    const float* x       = (const float*)d_in[0];
    const int*   ei      = (const int*)d_in[1];
    const float* gf      = (const float*)d_in[2];
    const float* node_W  = (const float*)d_in[3];
    const float* node_b  = (const float*)d_in[4];
    const float* nbr_W   = (const float*)d_in[5];
    const float* nbr_b   = (const float*)d_in[6];
    const float* gud_W   = (const float*)d_in[7];
    const float* gud_b   = (const float*)d_in[8];
    const float* enc_W   = (const float*)d_in[9];
    const float* enc_b   = (const float*)d_in[10];
    const float* vp_W1   = (const float*)d_in[11];
    const float* vp_b1   = (const float*)d_in[12];
    const float* vp_W2   = (const float*)d_in[13];
    const float* vp_b2   = (const float*)d_in[14];
    const float* pol_W1  = (const float*)d_in[15];
    const float* pol_b1  = (const float*)d_in[16];
    const float* pol_W2  = (const float*)d_in[17];
    const float* pol_b2  = (const float*)d_in[18];
    float* out = (float*)d_out;

    fold_kernel<<<dim3(4, 3), 256>>>(node_W, nbr_W, gud_W, enc_W);
    cb_kernel<<<1, 128>>>(node_b, nbr_b, gud_b, enc_W, enc_b);

    cudaFuncSetAttribute(node_mma_persist,
                         cudaFuncAttributeMaxDynamicSharedMemorySize, NSMEM);
    node_mma_persist<<<NODE_GRID, 256, NSMEM>>>(x, gf);

    cudaFuncSetAttribute(edge_kernel_mma,
                         cudaFuncAttributeMaxDynamicSharedMemorySize, SMEM_E);
    edge_kernel_mma<<<NGRID, 320, SMEM_E>>>(ei, vp_W1, vp_b1, vp_W2, vp_b2,
                                            pol_W1, pol_b1, pol_W2, pol_b2, out);
}

// round 8
// speedup vs baseline: 1.1139x; 1.1139x over previous
#include <cuda_runtime.h>
#include <cuda_bf16.h>
#include <math.h>
#include <stdint.h>

#define NN 50000
#define NE 800000
#define C 128

// Scratch (device globals; no allocation allowed)
// g_M1/2/3 hold the folded matrices TRANSPOSED: g_M[j*C + i] = M[i][j]
__device__ float g_M1[C * C];
__device__ float g_M2[C * C];
__device__ float g_M3[C * C];
__device__ float g_cb[C];
__device__ float g_A[NN * C];
__device__ float g_B[NN * C];

__device__ __forceinline__ uint32_t smem_u32(const void* p) {
    uint32_t a;
    asm("{ .reg .u64 t; cvta.to.shared.u64 t, %1; cvt.u32.u64 %0, t; }"
        : "=r"(a) : "l"(p));
    return a;
}
__device__ __forceinline__ void ldsm_x4(uint32_t* r, uint32_t addr) {
    asm volatile("ldmatrix.sync.aligned.m8n8.x4.shared.b16 {%0,%1,%2,%3}, [%4];"
                 : "=r"(r[0]), "=r"(r[1]), "=r"(r[2]), "=r"(r[3]) : "r"(addr));
}
__device__ __forceinline__ void mma_bf16(float* c, const uint32_t* a,
                                         uint32_t b0, uint32_t b1) {
    asm volatile(
        "mma.sync.aligned.m16n8k16.row.col.f32.bf16.bf16.f32 "
        "{%0,%1,%2,%3}, {%4,%5,%6,%7}, {%8,%9}, {%0,%1,%2,%3};"
        : "+f"(c[0]), "+f"(c[1]), "+f"(c[2]), "+f"(c[3])
        : "r"(a[0]), "r"(a[1]), "r"(a[2]), "r"(a[3]), "r"(b0), "r"(b1));
}

#define PITCH 272

// ---------------------------------------------------------------------------
// K1: fold the three input linears through enc_W. Stores TRANSPOSED:
// g_M[j*C+i] = sum_h W[i][h]*E[h][j]  (node kernel then reads coalesced).
// ---------------------------------------------------------------------------
__global__ void fold_kernel(const float* __restrict__ node_W,
                            const float* __restrict__ nbr_W,
                            const float* __restrict__ gud_W,
                            const float* __restrict__ enc_W) {
    int m = blockIdx.y;
    const float* W = (m == 0) ? node_W : ((m == 1) ? nbr_W : gud_W);
    const float* E = enc_W + m * C * C;
    float* M = (m == 0) ? g_M1 : ((m == 1) ? g_M2 : g_M3);

    int j = threadIdx.x & 127;
    int iq = threadIdx.x >> 7;
    int i0 = blockIdx.x * 32;
    for (int i = i0 + iq; i < i0 + 32; i += 2) {
        float s = 0.f;
#pragma unroll 4
        for (int h = 0; h < C; h++) s += W[i * C + h] * E[h * C + j];
        M[j * C + i] = s;   // transposed store
    }
}

__global__ void cb_kernel(const float* __restrict__ node_b,
                          const float* __restrict__ nbr_b,
                          const float* __restrict__ gud_b,
                          const float* __restrict__ enc_W,
                          const float* __restrict__ enc_b) {
    int j = threadIdx.x;
    float s = enc_b[j];
    for (int h = 0; h < C; h++) s += node_b[h] * enc_W[h * C + j];
    for (int h = 0; h < C; h++) s += nbr_b[h] * enc_W[(C + h) * C + j];
    for (int h = 0; h < C; h++) s += gud_b[h] * enc_W[(2 * C + h) * C + j];
    g_cb[j] = s;
}

// ---------------------------------------------------------------------------
// K2: WARP-PRIVATE split-bf16 node precompute. 148 blocks x 256 threads.
// Phases: 0: g_A = x@M1 ; 1: g_B = x@M2 ; 2: g_B += g@M3.
// Each warp independently processes 16-row tiles (3125 tiles, stride 1184).
// No block barrier inside the tile loop; weights staged once per phase.
// Fragment epilogue: STS to warp's fp32 strip (pitch 544B), then coalesced
// STG.128 (and coalesced RMW for phase 2; same warp owns same rows per phase).
// SMEM: W hi @0 (34816), W lo @34816; warp strips @69632 + wid*8704.
// ---------------------------------------------------------------------------
#define NWB   69632
#define NSMEM 139264
#define NODE_GRID 148

__global__ __launch_bounds__(256, 1)
void node_mma_warp(const float* __restrict__ x, const float* __restrict__ g) {
    extern __shared__ float smf[];
    char* smc = (char*)smf;
    uint32_t su = smem_u32(smf);
    int tid = threadIdx.x;
    int tx = tid & 31, wid = tid >> 5;
    int gwid = blockIdx.x * 8 + wid;

    uint32_t a_row = (tx & 7) + 8 * ((tx >> 3) & 1);
    uint32_t a_k16 = (tx >> 4) * 16;
    uint32_t b_row = (tx & 7) + 8 * (tx >> 4);
    uint32_t b_k16 = ((tx >> 3) & 1) * 16;

    char* wbuf = smc + NWB + wid * 8704;       // A hi (4352) + A lo (4352)
    uint32_t wbu = su + NWB + wid * 8704;
    float* fbuf = (float*)wbuf;                 // reused fp32 strip, pitch 136 fl

    const int NTW = NN / 16;  // 3125 exact
    const int WSTRIDE = NODE_GRID * 8;  // 1184

    for (int ph = 0; ph < 3; ph++) {
        const float* Wm = (ph == 0) ? g_M1 : ((ph == 1) ? g_M2 : g_M3);
        const float* src = (ph == 2) ? g : x;
        float* dst = (ph == 0) ? g_A : g_B;

        __syncthreads();  // all warps done reading previous weights
        for (int idx = tid; idx < C * C; idx += 256) {
            int n = idx >> 7, k = idx & 127;
            float w = Wm[idx];  // coalesced (g_M transposed)
            __nv_bfloat16 h = __float2bfloat16(w);
            __nv_bfloat16 l = __float2bfloat16(w - __bfloat162float(h));
            *(__nv_bfloat16*)(smc + n * PITCH + k * 2) = h;
            *(__nv_bfloat16*)(smc + 34816 + n * PITCH + k * 2) = l;
        }
        __syncthreads();

        for (int t = gwid; t < NTW; t += WSTRIDE) {
            int row0 = t * 16;

            // ---- stage 16 rows split-bf16 (warp-private) ----
            __syncwarp();
#pragma unroll 4
            for (int m = 0; m < 16; m++) {
                float4 v = ((const float4*)(src + (size_t)(row0 + m) * C))[tx];
                __nv_bfloat162 h01 = __floats2bfloat162_rn(v.x, v.y);
                __nv_bfloat162 h23 = __floats2bfloat162_rn(v.z, v.w);
                __nv_bfloat162 l01 = __floats2bfloat162_rn(
                    v.x - __bfloat162float(h01.x), v.y - __bfloat162float(h01.y));
                __nv_bfloat162 l23 = __floats2bfloat162_rn(
                    v.z - __bfloat162float(h23.x), v.w - __bfloat162float(h23.y));
                uint2 hv, lv;
                hv.x = *(uint32_t*)&h01; hv.y = *(uint32_t*)&h23;
                lv.x = *(uint32_t*)&l01; lv.y = *(uint32_t*)&l23;
                *(uint2*)(wbuf + m * PITCH + tx * 8) = hv;
                *(uint2*)(wbuf + 4352 + m * PITCH + tx * 8) = lv;
            }
            __syncwarp();

            // ---- MMA: [16x128] x [128x128], 3-term split ----
            float acc[16][4];
#pragma unroll
            for (int a = 0; a < 16; a++)
#pragma unroll
                for (int b = 0; b < 4; b++) acc[a][b] = 0.f;

            for (int ks = 0; ks < 8; ks++) {
                uint32_t ah[4], al[4];
                uint32_t acol = ks * 32 + a_k16;
                ldsm_x4(ah, wbu + a_row * PITCH + acol);
                ldsm_x4(al, wbu + 4352 + a_row * PITCH + acol);
                uint32_t bcol = ks * 32 + b_k16;
#pragma unroll
                for (int np = 0; np < 8; np++) {
                    uint32_t bro = (np * 16 + b_row) * PITCH + bcol;
                    uint32_t bh[4], bl[4];
                    ldsm_x4(bh, su + bro);
                    ldsm_x4(bl, su + 34816 + bro);
                    mma_bf16(acc[2 * np], ah, bh[0], bh[1]);
                    mma_bf16(acc[2 * np], al, bh[0], bh[1]);
                    mma_bf16(acc[2 * np], ah, bl[0], bl[1]);
                    mma_bf16(acc[2 * np + 1], ah, bh[2], bh[3]);
                    mma_bf16(acc[2 * np + 1], al, bh[2], bh[3]);
                    mma_bf16(acc[2 * np + 1], ah, bl[2], bl[3]);
                }
            }
            __syncwarp();

            // ---- fragments -> fp32 strip (pitch 136 floats) ----
            {
                int r = tx >> 2, c2 = 2 * (tx & 3);
#pragma unroll
                for (int nf = 0; nf < 16; nf++) {
                    int col = nf * 8 + c2;
                    *(float2*)&fbuf[r * 136 + col] =
                        make_float2(acc[nf][0], acc[nf][1]);
                    *(float2*)&fbuf[(r + 8) * 136 + col] =
                        make_float2(acc[nf][2], acc[nf][3]);
                }
            }
            __syncwarp();

            // ---- coalesced writeback (RMW for phase 2) ----
#pragma unroll 4
            for (int m = 0; m < 16; m++) {
                float4 v = *(float4*)&fbuf[m * 136 + tx * 4];
                float* p = dst + (size_t)(row0 + m) * C;
                if (ph == 2) {
                    float4 o = ((const float4*)p)[tx];
                    v.x += o.x; v.y += o.y; v.z += o.z; v.w += o.w;
                }
                ((float4*)p)[tx] = v;
            }
        }
    }
}

// ---------------------------------------------------------------------------
// K3: split-bf16 edge kernel (R4 structure: warp-private, no block barriers).
// SMEM (bytes):
//   [0..1536)        params: vb1[64] vw2[64] pb1[128] pw2[128] (floats)
//   [2048..71680)    A: 8 warps x (hi 16x272B + lo 16x272B) = 8704 B/warp
//   [71680..123904)  B hi: 192 rows x 272 B
//   [123904..176128) B lo
// ---------------------------------------------------------------------------
#define A_OFF    2048
#define A_WARP   (2 * 16 * PITCH)          // 8704
#define B_H_OFF  (A_OFF + 8 * A_WARP)      // 71680
#define B_L_OFF  (B_H_OFF + 192 * PITCH)   // 123904
#define SMEM_E   (B_L_OFF + 192 * PITCH)   // 176128
#define NGRID    148

__global__ __launch_bounds__(256, 1)
void edge_kernel_mma(const int* __restrict__ ei,
                     const float* __restrict__ vp_W1, const float* __restrict__ vp_b1,
                     const float* __restrict__ vp_W2, const float* __restrict__ vp_b2,
                     const float* __restrict__ pol_W1, const float* __restrict__ pol_b1,
                     const float* __restrict__ pol_W2, const float* __restrict__ pol_b2,
                     float* __restrict__ out) {
    extern __shared__ float smf[];
    char* smc = (char*)smf;
    uint32_t su = smem_u32(smf);
    int tid = threadIdx.x;
    int tx = tid & 31, wid = tid >> 5;

    // --- stage split weights B[n][k], n<64: vp_W1, else pol_W1 ---
    for (int idx = tid; idx < 192 * C; idx += 256) {
        int n = idx >> 7, k = idx & 127;
        float w = (n < 64) ? vp_W1[k * 64 + n] : pol_W1[k * C + (n - 64)];
        __nv_bfloat16 wh = __float2bfloat16(w);
        __nv_bfloat16 wl = __float2bfloat16(w - __bfloat162float(wh));
        *(__nv_bfloat16*)(smc + B_H_OFF + n * PITCH + k * 2) = wh;
        *(__nv_bfloat16*)(smc + B_L_OFF + n * PITCH + k * 2) = wl;
    }
    if (tid < 64) { smf[tid] = vp_b1[tid]; smf[64 + tid] = vp_W2[tid]; }
    if (tid < 128) { smf[128 + tid] = pol_b1[tid]; smf[256 + tid] = pol_W2[tid]; }
    __syncthreads();

    float vb2v = vp_b2[0], pb2v = pol_b2[0];
    float4 cb4 = ((const float4*)g_cb)[tx];
    if (blockIdx.x == 0 && tid == 0) out[3L * NE] = 0.f;  // value_loss

    uint32_t awu = su + A_OFF + wid * A_WARP;
    uint32_t a_row = (tx & 7) + 8 * ((tx >> 3) & 1);
    uint32_t a_k16 = (tx >> 4) * 16;
    uint32_t b_row = (tx & 7) + 8 * (tx >> 4);
    uint32_t b_k16 = ((tx >> 3) & 1) * 16;

    const int ntiles = NE / 128;  // 6250
    for (int t = blockIdx.x; t < ntiles; t += NGRID) {
        long base = (long)t * 128 + wid * 16;

        __syncwarp();
#pragma unroll 4
        for (int m = 0; m < 16; m++) {
            int rr = ei[base + m];
            int cc = ei[NE + base + m];
            float4 a = ((const float4*)(g_A + (size_t)rr * C))[tx];
            float4 b = ((const float4*)(g_B + (size_t)cc * C))[tx];
            float z0 = fmaxf(a.x + b.x + cb4.x, 0.f);
            float z1 = fmaxf(a.y + b.y + cb4.y, 0.f);
            float z2 = fmaxf(a.z + b.z + cb4.z, 0.f);
            float z3 = fmaxf(a.w + b.w + cb4.w, 0.f);
            __nv_bfloat162 h01 = __floats2bfloat162_rn(z0, z1);
            __nv_bfloat162 h23 = __floats2bfloat162_rn(z2, z3);
            __nv_bfloat162 l01 = __floats2bfloat162_rn(
                z0 - __bfloat162float(h01.x), z1 - __bfloat162float(h01.y));
            __nv_bfloat162 l23 = __floats2bfloat162_rn(
                z2 - __bfloat162float(h23.x), z3 - __bfloat162float(h23.y));
            uint2 hv, lv;
            hv.x = *(uint32_t*)&h01; hv.y = *(uint32_t*)&h23;
            lv.x = *(uint32_t*)&l01; lv.y = *(uint32_t*)&l23;
            *(uint2*)(smc + (awu - su) + m * PITCH + tx * 8) = hv;
            *(uint2*)(smc + (awu - su) + 16 * PITCH + m * PITCH + tx * 8) = lv;
        }
        __syncwarp();

        float acc[24][4];
#pragma unroll
        for (int a = 0; a < 24; a++)
#pragma unroll
            for (int b = 0; b < 4; b++) acc[a][b] = 0.f;

        for (int ks = 0; ks < 8; ks++) {
            uint32_t ah[4], al[4];
            uint32_t acol = ks * 32 + a_k16;
            ldsm_x4(ah, awu + a_row * PITCH + acol);
            ldsm_x4(al, awu + 16 * PITCH + a_row * PITCH + acol);
            uint32_t bcol = ks * 32 + b_k16;
#pragma unroll
            for (int np = 0; np < 12; np++) {
                uint32_t bro = (np * 16 + b_row) * PITCH + bcol;
                uint32_t bh[4], bl[4];
                ldsm_x4(bh, su + B_H_OFF + bro);
                ldsm_x4(bl, su + B_L_OFF + bro);
                mma_bf16(acc[2 * np], ah, bh[0], bh[1]);
                mma_bf16(acc[2 * np], al, bh[0], bh[1]);
                mma_bf16(acc[2 * np], ah, bl[0], bl[1]);
                mma_bf16(acc[2 * np + 1], ah, bh[2], bh[3]);
                mma_bf16(acc[2 * np + 1], al, bh[2], bh[3]);
                mma_bf16(acc[2 * np + 1], ah, bl[2], bl[3]);
            }
        }

        float vr = 0.f, vr8 = 0.f, lr = 0.f, lr8 = 0.f;
#pragma unroll
        for (int nt = 0; nt < 24; nt++) {
            int c0 = nt * 8 + 2 * (tx & 3);
            if (nt < 8) {
                float b0 = smf[c0], w0 = smf[64 + c0];
                float b1 = smf[c0 + 1], w1 = smf[64 + c0 + 1];
                vr  += fmaxf(acc[nt][0] + b0, 0.f) * w0 + fmaxf(acc[nt][1] + b1, 0.f) * w1;
                vr8 += fmaxf(acc[nt][2] + b0, 0.f) * w0 + fmaxf(acc[nt][3] + b1, 0.f) * w1;
            } else {
                int ix = c0 - 64;
                float b0 = smf[128 + ix], w0 = smf[256 + ix];
                float b1 = smf[128 + ix + 1], w1 = smf[256 + ix + 1];
                lr  += fmaxf(acc[nt][0] + b0, 0.f) * w0 + fmaxf(acc[nt][1] + b1, 0.f) * w1;
                lr8 += fmaxf(acc[nt][2] + b0, 0.f) * w0 + fmaxf(acc[nt][3] + b1, 0.f) * w1;
            }
        }
#pragma unroll
        for (int off = 1; off <= 2; off <<= 1) {
            vr  += __shfl_xor_sync(0xffffffffu, vr, off);
            vr8 += __shfl_xor_sync(0xffffffffu, vr8, off);
            lr  += __shfl_xor_sync(0xffffffffu, lr, off);
            lr8 += __shfl_xor_sync(0xffffffffu, lr8, off);
        }
        if ((tx & 3) == 0) {
            int r = tx >> 2;
            long e0 = base + r;
            long e1 = base + r + 8;
            float v0 = vr + vb2v, v1 = vr8 + vb2v;
            float p0 = 1.f / (1.f + expf(-(lr + pb2v)));
            float p1 = 1.f / (1.f + expf(-(lr8 + pb2v)));
            out[e0] = v0;
            out[e1] = v1;
            out[NE + e0] = p0;
            out[NE + e1] = p1;
            out[2L * NE + e0] = (p0 > 0.5f) ? 1.f : 0.f;
            out[2L * NE + e1] = (p1 > 0.5f) ? 1.f : 0.f;
        }
    }
}

// ---------------------------------------------------------------------------
extern "C" void kernel_launch(void* const* d_in, const int* in_sizes, int n_in,
                              void* d_out, int out_size) {
    const float* x       = (const float*)d_in[0];
    const int*   ei      = (const int*)d_in[1];
    const float* gf      = (const float*)d_in[2];
    const float* node_W  = (const float*)d_in[3];
    const float* node_b  = (const float*)d_in[4];
    const float* nbr_W   = (const float*)d_in[5];
    const float* nbr_b   = (const float*)d_in[6];
    const float* gud_W   = (const float*)d_in[7];
    const float* gud_b   = (const float*)d_in[8];
    const float* enc_W   = (const float*)d_in[9];
    const float* enc_b   = (const float*)d_in[10];
    const float* vp_W1   = (const float*)d_in[11];
    const float* vp_b1   = (const float*)d_in[12];
    const float* vp_W2   = (const float*)d_in[13];
    const float* vp_b2   = (const float*)d_in[14];
    const float* pol_W1  = (const float*)d_in[15];
    const float* pol_b1  = (const float*)d_in[16];
    const float* pol_W2  = (const float*)d_in[17];
    const float* pol_b2  = (const float*)d_in[18];
    float* out = (float*)d_out;

    fold_kernel<<<dim3(4, 3), 256>>>(node_W, nbr_W, gud_W, enc_W);
    cb_kernel<<<1, 128>>>(node_b, nbr_b, gud_b, enc_W, enc_b);

    cudaFuncSetAttribute(node_mma_warp,
                         cudaFuncAttributeMaxDynamicSharedMemorySize, NSMEM);
    node_mma_warp<<<NODE_GRID, 256, NSMEM>>>(x, gf);

    cudaFuncSetAttribute(edge_kernel_mma,
                         cudaFuncAttributeMaxDynamicSharedMemorySize, SMEM_E);
    edge_kernel_mma<<<NGRID, 256, SMEM_E>>>(ei, vp_W1, vp_b1, vp_W2, vp_b2,
                                            pol_W1, pol_b1, pol_W2, pol_b2, out);
}